// round 14
// baseline (speedup 1.0000x reference)
#include <cuda_runtime.h>
#include <math.h>
#include <stdint.h>

// Problem dims (LinearAttnBlock: B=8, C=256, H=W=64)
#define BATCH 8
#define CDIM  256
#define NDIM  4096
#define GRP   32
#define KVSPLIT 8

// ---------------- scratch (__device__ globals; no allocation allowed) ------
__device__ float  g_h  [(size_t)BATCH * CDIM * NDIM];            // tf32(GN(x))
__device__ float  g_qkv[(size_t)BATCH * 2 * CDIM * NDIM];        // [b][q/k][c][n] tf32
__device__ float  g_Sp [(size_t)KVSPLIT * BATCH * CDIM * CDIM];  // S split partials
__device__ float  g_S  [BATCH * CDIM * CDIM];                    // [b][c][e] = K.h^T
__device__ float  g_M  [BATCH * CDIM * CDIM];                    // [b][o][c] tf32
__device__ float  g_U  [CDIM * CDIM];                            // wo @ Wv
__device__ float  g_wt [CDIM];                                   // wo @ bv
__device__ float  g_k1 [BATCH * CDIM];                           // rowsum of K
__device__ float  g_wqr[CDIM * CDIM];                            // tf32(wq)
__device__ float  g_wkr[CDIM * CDIM];                            // tf32(wk)
__device__ float2 g_stats[BATCH * GRP];                          // (mean, rstd)

// ---------------- tf32 mma.sync micro-kernel ------------------------------
static __device__ __forceinline__ uint32_t to_tf32(float f) {
    uint32_t r;
    asm("cvt.rna.tf32.f32 %0, %1;" : "=r"(r) : "f"(f));
    return r;
}

static __device__ __forceinline__ void mma_tf32(float c[4], const uint4& a, const uint2& b) {
    asm volatile(
        "mma.sync.aligned.m16n8k8.row.col.f32.tf32.tf32.f32 "
        "{%0,%1,%2,%3}, {%4,%5,%6,%7}, {%8,%9}, {%0,%1,%2,%3};"
        : "+f"(c[0]), "+f"(c[1]), "+f"(c[2]), "+f"(c[3])
        : "r"(a.x), "r"(a.y), "r"(a.z), "r"(a.w), "r"(b.x), "r"(b.y));
}

// C[128,128] += A[128, NC*16] * B(k,n)[NC*16, 128] (operands already
// tf32-valued fp32 in gmem -> staging is a raw bit copy, NO cvt, NO GN).
// BK=16 double-buffered stages; 2 CTAs/SM via __launch_bounds__(256,2).
// A layout: word = ((mt*2+ks)*32 + g*4 + t)*4 + ahi + 2*kh, xor ((g>>1)&3)<<2
// B layout: word = ((nt2*2+ks)*32 + g*4 + t)*4 + (nt&1)*2 + kh,
//           xor ((nt2 ^ (g>>1))&7)<<2
// Stores STS.64 (2-way max conflict); frag loads lds.128 conflict-free.
// BMODE 0: B source rows = k (ldb per k-row). BMODE 1: B source rows = col
// (ldb per col, k contiguous).
template <int NC, int BMODE>
static __device__ __forceinline__ void mma_block(
    const float* __restrict__ A, int lda,
    const float* __restrict__ B, int ldb,
    uint32_t* __restrict__ As, uint32_t* __restrict__ Bs,
    float C[2][8][4])
{
    static_assert((NC & 1) == 0, "NC must be even");
    const int tid = threadIdx.x;
    const int lane = tid & 31, wid = tid >> 5;
    const int wm = wid & 3, wn = wid >> 2;

    // ---- A staging: thread -> (row-pair rp, k-quad j) ----
    const int arp = tid >> 2, aj = tid & 3;
    const int amt = arp >> 3, ag = arp & 7;
    const int arow = amt * 16 + ag;            // second row = arow + 8
    const int akoff = aj << 2;                 // 4 contiguous k
    int aidx[4];
    {
        const int aks = aj >> 1, akh = aj & 1;
        const int axor = ((ag >> 1) & 3) << 2;
        const int aw0 = ((amt * 2 + aks) * 32 + ag * 4) * 4 + 2 * akh;
        #pragma unroll
        for (int t = 0; t < 4; t++) aidx[t] = (aw0 + 4 * t) ^ axor;
    }

    // ---- B staging mapping + loop-invariant store indices ----
    int bidx[4];
    int b0r0 = 0, b0r1 = 0;          // BMODE0: two k-rows within chunk
    const int b0n = lane << 2;       // BMODE0: 4 n's
    const float* pBbase = B;
    if (BMODE == 0) {
        const int ks = wid >> 2, t = wid & 3;
        b0r0 = ks * 8 + t; b0r1 = b0r0 + 4;
        #pragma unroll
        for (int m = 0; m < 4; m++) {
            const int n = b0n + m;
            const int gg = n & 7, ntl = (n >> 3) & 1, nt2 = n >> 4;
            const int w = ((nt2 * 2 + ks) * 32 + gg * 4 + t) * 4 + ntl * 2;
            bidx[m] = w ^ (((nt2 ^ (gg >> 1)) & 7) << 2);
        }
    } else {
        const int b1col = tid >> 1;
        const int ks = tid & 1;
        const int gg = b1col & 7, ntl = (b1col >> 3) & 1, nt2 = b1col >> 4;
        #pragma unroll
        for (int t = 0; t < 4; t++) {
            const int w = ((nt2 * 2 + ks) * 32 + gg * 4 + t) * 4 + ntl * 2;
            bidx[t] = w ^ (((nt2 ^ (gg >> 1)) & 7) << 2);
        }
        pBbase = B + (size_t)b1col * ldb + ks * 8;
    }
    const float* pAbase = A + (size_t)arow * lda + akoff;

    // ---- precomputed frag word-indices (loop-invariant) ----
    int afi[2][2], bfi[2][4];
    {
        const int axorf = ((lane >> 3) & 3) << 2;
        #pragma unroll
        for (int mt = 0; mt < 2; mt++)
            #pragma unroll
            for (int ks = 0; ks < 2; ks++)
                afi[mt][ks] = ((((wm * 2 + mt) * 2 + ks) * 32 + lane) * 4) ^ axorf;
        #pragma unroll
        for (int ks = 0; ks < 2; ks++)
            #pragma unroll
            for (int q = 0; q < 4; q++) {
                const int NT2 = wn * 4 + q;
                bfi[ks][q] = (((NT2 * 2 + ks) * 32 + lane) * 4)
                             ^ (((NT2 ^ (lane >> 3)) & 7) << 2);
            }
    }

    float4 ra0, ra1, rb0, rb1;

    // ---- prefetch helper (loads chunk ic into regs; pure bit moves) ----
    auto prefetch = [&](int ic) {
        const float* pa = pAbase + ic * 16;
        ra0 = *(const float4*)pa;
        ra1 = *(const float4*)(pa + 8 * (size_t)lda);
        if (BMODE == 0) {
            const int c0 = ic * 16 + b0r0, c1 = c0 + 4;
            rb0 = *(const float4*)(pBbase + (size_t)c0 * ldb + b0n);
            rb1 = *(const float4*)(pBbase + (size_t)c1 * ldb + b0n);
        } else {
            const float* pb = pBbase + ic * 16;
            rb0 = *(const float4*)pb;
            rb1 = *(const float4*)(pb + 4);
        }
    };

    // ---- one pipeline step on a stage ----
    auto chunk = [&](uint32_t* __restrict__ Asb, uint32_t* __restrict__ Bsb,
                     int inext, bool dopf) {
        {   // store regs -> SMEM stage (raw bits, STS.64, precomputed addrs)
            const float a0[4] = {ra0.x, ra0.y, ra0.z, ra0.w};
            const float a1[4] = {ra1.x, ra1.y, ra1.z, ra1.w};
            #pragma unroll
            for (int t = 0; t < 4; t++) {
                uint2 st;
                st.x = __float_as_uint(a0[t]); st.y = __float_as_uint(a1[t]);
                *(uint2*)&Asb[aidx[t]] = st;
            }
            const float v0[4] = {rb0.x, rb0.y, rb0.z, rb0.w};
            const float v1[4] = {rb1.x, rb1.y, rb1.z, rb1.w};
            #pragma unroll
            for (int m = 0; m < 4; m++) {
                uint2 st;
                st.x = __float_as_uint(v0[m]); st.y = __float_as_uint(v1[m]);
                *(uint2*)&Bsb[bidx[m]] = st;
            }
        }
        __syncthreads();
        if (dopf) prefetch(inext);   // overlaps with mma below
        #pragma unroll
        for (int ks = 0; ks < 2; ks++) {
            uint4 af0 = *(const uint4*)&Asb[afi[0][ks]];
            uint4 af1 = *(const uint4*)&Asb[afi[1][ks]];
            #pragma unroll
            for (int q = 0; q < 4; q++) {
                uint4 bf = *(const uint4*)&Bsb[bfi[ks][q]];
                const uint2 blo = make_uint2(bf.x, bf.y);
                const uint2 bhi = make_uint2(bf.z, bf.w);
                mma_tf32(C[0][2 * q + 0], af0, blo);
                mma_tf32(C[0][2 * q + 1], af0, bhi);
                mma_tf32(C[1][2 * q + 0], af1, blo);
                mma_tf32(C[1][2 * q + 1], af1, bhi);
            }
        }
    };

    prefetch(0);
    #pragma unroll 1
    for (int i = 0; i < NC; i += 2) {
        chunk(As, Bs, i + 1, true);                       // stage 0
        chunk(As + 2048, Bs + 2048, i + 2, i + 2 < NC);   // stage 1
    }
    __syncthreads();
}

// ---------------------------------------------------------------------------
// K1: GroupNorm statistics (one block per (b,g)) + zero g_k1 for this replay.
// ---------------------------------------------------------------------------
__global__ __launch_bounds__(256) void k_stats(const float* __restrict__ x) {
    const int bg = blockIdx.x;
    if (threadIdx.x < 8) g_k1[bg * 8 + threadIdx.x] = 0.f;
    const float4* p = reinterpret_cast<const float4*>(x + (size_t)bg * 8 * NDIM);
    float s = 0.f, s2 = 0.f;
    for (int i = threadIdx.x; i < 8 * NDIM / 4; i += 256) {
        float4 v = p[i];
        s  += v.x + v.y + v.z + v.w;
        s2 += v.x * v.x + v.y * v.y + v.z * v.z + v.w * v.w;
    }
    __shared__ float sh0[8], sh1[8];
    #pragma unroll
    for (int o = 16; o > 0; o >>= 1) {
        s  += __shfl_down_sync(0xffffffffu, s,  o);
        s2 += __shfl_down_sync(0xffffffffu, s2, o);
    }
    const int lane = threadIdx.x & 31, w = threadIdx.x >> 5;
    if (lane == 0) { sh0[w] = s; sh1[w] = s2; }
    __syncthreads();
    if (w == 0) {
        s  = (lane < 8) ? sh0[lane] : 0.f;
        s2 = (lane < 8) ? sh1[lane] : 0.f;
        #pragma unroll
        for (int o = 4; o > 0; o >>= 1) {
            s  += __shfl_down_sync(0xffffffffu, s,  o);
            s2 += __shfl_down_sync(0xffffffffu, s2, o);
        }
        if (lane == 0) {
            const float inv = 1.f / (8.f * NDIM);
            float mean = s * inv;
            float var  = s2 * inv - mean * mean;
            g_stats[bg] = make_float2(mean, rsqrtf(var + 1e-6f));
        }
    }
}

// ---------------------------------------------------------------------------
// K2: h = tf32_round(GN(x)).  One block per (b, c) row; 4 float4/thread.
// ---------------------------------------------------------------------------
__global__ __launch_bounds__(256) void k_ht(const float* __restrict__ x,
                                            const float* __restrict__ gamma,
                                            const float* __restrict__ beta) {
    const int c = blockIdx.x, b = blockIdx.y;
    float2 ms = g_stats[b * GRP + (c >> 3)];
    const float sc = ms.y * gamma[c];
    const float sh = fmaf(-ms.x, sc, beta[c]);
    const float4* src = (const float4*)(x  + ((size_t)b * CDIM + c) * NDIM);
    uint4*       dst = (uint4*)(g_h + ((size_t)b * CDIM + c) * NDIM);
    #pragma unroll
    for (int q = 0; q < 4; q++) {
        const int i = q * 256 + threadIdx.x;
        float4 v = src[i];
        uint4 o;
        o.x = to_tf32(fmaf(v.x, sc, sh));
        o.y = to_tf32(fmaf(v.y, sc, sh));
        o.z = to_tf32(fmaf(v.z, sc, sh));
        o.w = to_tf32(fmaf(v.w, sc, sh));
        dst[i] = o;
    }
}

// ---------------------------------------------------------------------------
// K3: U = wo @ Wv, wt = wo @ bv, and tf32-rounded copies of wq, wk.
// ---------------------------------------------------------------------------
__global__ __launch_bounds__(256) void k_prep(const float* __restrict__ wo,
                                              const float* __restrict__ wv,
                                              const float* __restrict__ bv,
                                              const float* __restrict__ wq,
                                              const float* __restrict__ wk) {
    const int o0 = blockIdx.y * 64, e0 = blockIdx.x * 64;
    const int tid = threadIdx.x;
    const int blk = blockIdx.y * 4 + blockIdx.x;
    // tf32-round weight copies (each block: 4096 elems of each matrix)
    for (int i = tid; i < 4096; i += 256) {
        const int idx = blk * 4096 + i;
        g_wqr[idx] = __uint_as_float(to_tf32(wq[idx]));
        g_wkr[idx] = __uint_as_float(to_tf32(wk[idx]));
    }
    if (blockIdx.x == 0 && tid < 64) {        // wt for this o-range
        const float* wr = wo + (size_t)(o0 + tid) * CDIM;
        float s = 0.f;
        for (int d = 0; d < CDIM; d += 4) {
            float4 w4 = *(const float4*)(wr + d);
            float4 b4 = *(const float4*)(bv + d);
            s += w4.x * b4.x + w4.y * b4.y + w4.z * b4.z + w4.w * b4.w;
        }
        g_wt[o0 + tid] = s;
    }

    __shared__ float As[16][64];
    __shared__ float Bs[16][64];
    const int arow = tid >> 2, acol = (tid & 3) << 2;   // A^T staging
    const int brow = tid >> 4, bcol = (tid & 15) << 2;  // B row-major staging
    const int tx = (tid & 15) << 2, ty = (tid >> 4) << 2;

    float acc[4][4];
    #pragma unroll
    for (int i = 0; i < 4; i++)
        #pragma unroll
        for (int j = 0; j < 4; j++) acc[i][j] = 0.f;

    for (int k0 = 0; k0 < CDIM; k0 += 16) {
        float4 av = *(const float4*)(wo + (size_t)(o0 + arow) * CDIM + k0 + acol);
        As[acol + 0][arow] = av.x; As[acol + 1][arow] = av.y;
        As[acol + 2][arow] = av.z; As[acol + 3][arow] = av.w;
        *(float4*)&Bs[brow][bcol] =
            *(const float4*)(wv + (size_t)(k0 + brow) * CDIM + e0 + bcol);
        __syncthreads();
        #pragma unroll
        for (int k = 0; k < 16; k++) {
            float4 a4 = *(const float4*)&As[k][ty];
            float4 b4 = *(const float4*)&Bs[k][tx];
            float a[4] = {a4.x, a4.y, a4.z, a4.w};
            float bb[4] = {b4.x, b4.y, b4.z, b4.w};
            #pragma unroll
            for (int i = 0; i < 4; i++)
                #pragma unroll
                for (int j = 0; j < 4; j++)
                    acc[i][j] = fmaf(a[i], bb[j], acc[i][j]);
        }
        __syncthreads();
    }
    #pragma unroll
    for (int i = 0; i < 4; i++)
        *(float4*)(g_U + (size_t)(o0 + ty + i) * CDIM + e0 + tx) =
            make_float4(acc[i][0], acc[i][1], acc[i][2], acc[i][3]);
}

// ---------------------------------------------------------------------------
// K4: Q,K = W_{q,k} @ h via tf32 mma.sync.  bias + elu+1 + tf32-round
// epilogue; K path also accumulates k1 rowsums (atomicAdd).
// ---------------------------------------------------------------------------
__global__ __launch_bounds__(256, 2) void k_qkv_t(
    const float* __restrict__ bq, const float* __restrict__ bk) {
    extern __shared__ uint32_t smp[];
    uint32_t* As = smp;            // 2 x 2048
    uint32_t* Bs = smp + 4096;     // 2 x 2048
    const int b  = blockIdx.z;
    const int by = blockIdx.y;            // 0..3
    const int which = by >> 1;            // 0=q 1=k
    const int m0 = (by & 1) * 128;
    const int n0 = blockIdx.x * 128;
    const float* W    = which == 0 ? g_wqr : g_wkr;
    const float* bias = which == 0 ? bq : bk;

    float C[2][8][4];
    #pragma unroll
    for (int mt = 0; mt < 2; mt++)
        #pragma unroll
        for (int nt = 0; nt < 8; nt++)
            #pragma unroll
            for (int r = 0; r < 4; r++) C[mt][nt][r] = 0.f;

    mma_block<16, 0>(W + (size_t)m0 * CDIM, CDIM,
                     g_h + (size_t)b * CDIM * NDIM + n0, NDIM, As, Bs, C);

    const int lane = threadIdx.x & 31, wid = threadIdx.x >> 5;
    const int g = lane >> 2, t = lane & 3, wm = wid & 3, wn = wid >> 2;
    float* outp = g_qkv + (((size_t)b * 2 + which) * CDIM + m0) * NDIM + n0;
    float rs0[2] = {0.f, 0.f}, rs1[2] = {0.f, 0.f};
    #pragma unroll
    for (int mt = 0; mt < 2; mt++) {
        const int r0 = wm * 32 + mt * 16 + g;
        const float b0v = bias[m0 + r0], b1v = bias[m0 + r0 + 8];
        #pragma unroll
        for (int nt = 0; nt < 8; nt++) {
            const int col = wn * 64 + nt * 8 + 2 * t;
            float v0 = C[mt][nt][0] + b0v, v1 = C[mt][nt][1] + b0v;
            float v2 = C[mt][nt][2] + b1v, v3 = C[mt][nt][3] + b1v;
            v0 = (v0 > 0.f) ? (v0 + 1.f) : __expf(v0);   // elu+1 (fast exp)
            v1 = (v1 > 0.f) ? (v1 + 1.f) : __expf(v1);
            v2 = (v2 > 0.f) ? (v2 + 1.f) : __expf(v2);
            v3 = (v3 > 0.f) ? (v3 + 1.f) : __expf(v3);
            v0 = __uint_as_float(to_tf32(v0));           // pre-round for mma
            v1 = __uint_as_float(to_tf32(v1));
            v2 = __uint_as_float(to_tf32(v2));
            v3 = __uint_as_float(to_tf32(v3));
            rs0[mt] += v0 + v1;
            rs1[mt] += v2 + v3;
            *(float2*)(outp + (size_t)r0 * NDIM + col)       = make_float2(v0, v1);
            *(float2*)(outp + (size_t)(r0 + 8) * NDIM + col) = make_float2(v2, v3);
        }
    }
    if (which == 1) {   // k1[c] = sum_n K[c,n]
        #pragma unroll
        for (int mt = 0; mt < 2; mt++) {
            float a = rs0[mt], c2 = rs1[mt];
            a  += __shfl_xor_sync(0xffffffffu, a,  1);
            a  += __shfl_xor_sync(0xffffffffu, a,  2);
            c2 += __shfl_xor_sync(0xffffffffu, c2, 1);
            c2 += __shfl_xor_sync(0xffffffffu, c2, 2);
            if (t == 0) {
                const int r0 = wm * 32 + mt * 16 + g;
                atomicAdd(&g_k1[b * CDIM + m0 + r0], a);
                atomicAdd(&g_k1[b * CDIM + m0 + r0 + 8], c2);
            }
        }
    }
}

// ---------------------------------------------------------------------------
// K5: S partials. Sp[sp][b][c][e] = sum_{n in split} K[c,n] * h[e,n].
// ---------------------------------------------------------------------------
__global__ __launch_bounds__(256, 2) void k_S() {
    extern __shared__ uint32_t smp[];
    uint32_t* As = smp;
    uint32_t* Bs = smp + 4096;
    const int z = blockIdx.z;
    const int b = z / KVSPLIT, sp = z % KVSPLIT;
    const int c0 = blockIdx.y * 128, e0 = blockIdx.x * 128;
    const int nb = sp * (NDIM / KVSPLIT);
    const float* Kf = g_qkv + ((size_t)b * 2 + 1) * CDIM * NDIM;

    float C[2][8][4];
    #pragma unroll
    for (int mt = 0; mt < 2; mt++)
        #pragma unroll
        for (int nt = 0; nt < 8; nt++)
            #pragma unroll
            for (int r = 0; r < 4; r++) C[mt][nt][r] = 0.f;

    mma_block<(NDIM / KVSPLIT) / 16, 1>(
        Kf + (size_t)c0 * NDIM + nb, NDIM,
        g_h + ((size_t)b * CDIM + e0) * NDIM + nb, NDIM, As, Bs, C);

    const int lane = threadIdx.x & 31, wid = threadIdx.x >> 5;
    const int g = lane >> 2, t = lane & 3, wm = wid & 3, wn = wid >> 2;
    float* dst = g_Sp + ((size_t)sp * BATCH + b) * CDIM * CDIM;
    #pragma unroll
    for (int mt = 0; mt < 2; mt++) {
        const int r0 = c0 + wm * 32 + mt * 16 + g;
        #pragma unroll
        for (int nt = 0; nt < 8; nt++) {
            const int col = e0 + wn * 64 + nt * 8 + 2 * t;
            *(float2*)(dst + (size_t)r0 * CDIM + col)       = make_float2(C[mt][nt][0], C[mt][nt][1]);
            *(float2*)(dst + (size_t)(r0 + 8) * CDIM + col) = make_float2(C[mt][nt][2], C[mt][nt][3]);
        }
    }
}

// ---------------------------------------------------------------------------
// K6: streaming reduction of the 8 S partials.
// ---------------------------------------------------------------------------
__global__ __launch_bounds__(256) void k_red() {
    const size_t i = (size_t)blockIdx.x * 256 + threadIdx.x;   // float4 idx
    const size_t SS = (size_t)BATCH * CDIM * CDIM / 4;
    const float4* p = reinterpret_cast<const float4*>(g_Sp);
    float4 a = p[i];
    #pragma unroll
    for (int s = 1; s < KVSPLIT; s++) {
        float4 v = p[i + (size_t)s * SS];
        a.x += v.x; a.y += v.y; a.z += v.z; a.w += v.w;
    }
    reinterpret_cast<float4*>(g_S)[i] = a;
}

// ---------------------------------------------------------------------------
// K7: M[b][o][c] = sum_e U[o,e] S[b][c,e] + wt[o]*k1[b][c], tf32-rounded.
// ---------------------------------------------------------------------------
__global__ __launch_bounds__(256) void k_M() {
    const int b  = blockIdx.z;
    const int o0 = blockIdx.y * 64, c0 = blockIdx.x * 64;
    const float* Sb = g_S + (size_t)b * CDIM * CDIM;

    __shared__ float As[16][64];
    __shared__ float Bs[16][64];
    const int tid  = threadIdx.x;
    const int arow = tid >> 2, acol = (tid & 3) << 2;
    const int tx = (tid & 15) << 2, ty = (tid >> 4) << 2;

    float acc[4][4];
    #pragma unroll
    for (int i = 0; i < 4; i++)
        #pragma unroll
        for (int j = 0; j < 4; j++) acc[i][j] = 0.f;

    for (int k0 = 0; k0 < CDIM; k0 += 16) {
        float4 av = *(const float4*)(g_U + (size_t)(o0 + arow) * CDIM + k0 + acol);
        As[acol + 0][arow] = av.x; As[acol + 1][arow] = av.y;
        As[acol + 2][arow] = av.z; As[acol + 3][arow] = av.w;
        float4 bv = *(const float4*)(Sb + (size_t)(c0 + arow) * CDIM + k0 + acol);
        Bs[acol + 0][arow] = bv.x; Bs[acol + 1][arow] = bv.y;
        Bs[acol + 2][arow] = bv.z; Bs[acol + 3][arow] = bv.w;
        __syncthreads();
        #pragma unroll
        for (int k = 0; k < 16; k++) {
            float4 a4 = *(const float4*)&As[k][ty];
            float4 b4 = *(const float4*)&Bs[k][tx];
            float a[4] = {a4.x, a4.y, a4.z, a4.w};
            float bb[4] = {b4.x, b4.y, b4.z, b4.w};
            #pragma unroll
            for (int i = 0; i < 4; i++)
                #pragma unroll
                for (int j = 0; j < 4; j++)
                    acc[i][j] = fmaf(a[i], bb[j], acc[i][j]);
        }
        __syncthreads();
    }
    float* Mb = g_M + (size_t)b * CDIM * CDIM;
    const float* k1b = g_k1 + b * CDIM;
    #pragma unroll
    for (int i = 0; i < 4; i++) {
        const float w = g_wt[o0 + ty + i];
        uint4 o;
        o.x = to_tf32(acc[i][0] + w * k1b[c0 + tx + 0]);
        o.y = to_tf32(acc[i][1] + w * k1b[c0 + tx + 1]);
        o.z = to_tf32(acc[i][2] + w * k1b[c0 + tx + 2]);
        o.w = to_tf32(acc[i][3] + w * k1b[c0 + tx + 3]);
        *(uint4*)(Mb + (size_t)(o0 + ty + i) * CDIM + c0 + tx) = o;
    }
}

// ---------------------------------------------------------------------------
// K8: out[b][o][n] = x[b][o][n] + M[b][o,:] . Q[:,n] + bo[o].
// ---------------------------------------------------------------------------
__global__ __launch_bounds__(256, 2) void k_out_t(const float* __restrict__ x,
                                                  const float* __restrict__ bo,
                                                  float* __restrict__ out) {
    extern __shared__ uint32_t smp[];
    uint32_t* As = smp;
    uint32_t* Bs = smp + 4096;
    const int b  = blockIdx.z;
    const int o0 = blockIdx.y * 128, n0 = blockIdx.x * 128;
    const float* Mb = g_M + (size_t)b * CDIM * CDIM;
    const float* Qf = g_qkv + (size_t)b * 2 * CDIM * NDIM;   // q plane [c][n]

    float C[2][8][4];
    #pragma unroll
    for (int mt = 0; mt < 2; mt++)
        #pragma unroll
        for (int nt = 0; nt < 8; nt++)
            #pragma unroll
            for (int r = 0; r < 4; r++) C[mt][nt][r] = 0.f;

    mma_block<16, 0>(Mb + (size_t)o0 * CDIM, CDIM, Qf + n0, NDIM, As, Bs, C);

    const int lane = threadIdx.x & 31, wid = threadIdx.x >> 5;
    const int g = lane >> 2, t = lane & 3, wm = wid & 3, wn = wid >> 2;
    const float* xb = x   + ((size_t)b * CDIM + o0) * NDIM + n0;
    float*       ob = out + ((size_t)b * CDIM + o0) * NDIM + n0;
    #pragma unroll
    for (int mt = 0; mt < 2; mt++) {
        const int r0 = wm * 32 + mt * 16 + g;
        const float b0v = bo[o0 + r0], b1v = bo[o0 + r0 + 8];
        #pragma unroll
        for (int nt = 0; nt < 8; nt++) {
            const int col = wn * 64 + nt * 8 + 2 * t;
            float2 x0 = *(const float2*)(xb + (size_t)r0 * NDIM + col);
            float2 x1 = *(const float2*)(xb + (size_t)(r0 + 8) * NDIM + col);
            *(float2*)(ob + (size_t)r0 * NDIM + col) =
                make_float2(C[mt][nt][0] + b0v + x0.x, C[mt][nt][1] + b0v + x0.y);
            *(float2*)(ob + (size_t)(r0 + 8) * NDIM + col) =
                make_float2(C[mt][nt][2] + b1v + x1.x, C[mt][nt][3] + b1v + x1.y);
        }
    }
}

// ---------------------------------------------------------------------------
#define MMA_SMEM 32768
extern "C" void kernel_launch(void* const* d_in, const int* in_sizes, int n_in,
                              void* d_out, int out_size) {
    const float* x     = (const float*)d_in[0];
    const float* gamma = (const float*)d_in[1];
    const float* beta  = (const float*)d_in[2];
    const float* wq    = (const float*)d_in[3];
    const float* bq    = (const float*)d_in[4];
    const float* wk    = (const float*)d_in[5];
    const float* bk    = (const float*)d_in[6];
    const float* wv    = (const float*)d_in[7];
    const float* bv    = (const float*)d_in[8];
    const float* wo    = (const float*)d_in[9];
    const float* bo    = (const float*)d_in[10];
    float* out = (float*)d_out;

    cudaFuncSetAttribute(k_qkv_t, cudaFuncAttributeMaxDynamicSharedMemorySize, MMA_SMEM);
    cudaFuncSetAttribute(k_S,     cudaFuncAttributeMaxDynamicSharedMemorySize, MMA_SMEM);
    cudaFuncSetAttribute(k_out_t, cudaFuncAttributeMaxDynamicSharedMemorySize, MMA_SMEM);

    k_stats<<<BATCH * GRP, 256>>>(x);
    k_ht<<<dim3(CDIM, BATCH), 256>>>(x, gamma, beta);
    k_prep<<<dim3(4, 4), 256>>>(wo, wv, bv, wq, wk);
    k_qkv_t<<<dim3(NDIM / 128, 4, BATCH), 256, MMA_SMEM>>>(bq, bk);
    k_S<<<dim3(2, 2, BATCH * KVSPLIT), 256, MMA_SMEM>>>();
    k_red<<<(BATCH * CDIM * CDIM) / (256 * 4), 256>>>();
    k_M<<<dim3(4, 4, BATCH), 256>>>();
    k_out_t<<<dim3(NDIM / 128, 2, BATCH), 256, MMA_SMEM>>>(x, bo, out);
}

// round 15
// speedup vs baseline: 1.1690x; 1.1690x over previous
#include <cuda_runtime.h>
#include <math.h>
#include <stdint.h>

// Problem dims (LinearAttnBlock: B=8, C=256, H=W=64)
#define BATCH 8
#define CDIM  256
#define NDIM  4096
#define GRP   32
#define KVSPLIT 8
#define CHUNK_WORDS 2048   // one perm chunk: 128 rows x 16 k = 8KB

// ---------------- scratch (__device__ globals; no allocation allowed) ------
__device__ float  g_h  [(size_t)BATCH * CDIM * NDIM];            // tf32(GN(x)) linear
__device__ float  g_q  [(size_t)BATCH * CDIM * NDIM];            // Q linear (tf32 vals)
__device__ float  g_kp [(size_t)BATCH * CDIM * NDIM];            // K, A-perm chunks
__device__ float  g_Sp [(size_t)KVSPLIT * BATCH * CDIM * CDIM];  // S split partials
__device__ float  g_S  [BATCH * CDIM * CDIM];                    // [b][c][e]
__device__ float  g_Mp [BATCH * CDIM * CDIM];                    // M, A-perm chunks
__device__ float  g_U  [CDIM * CDIM];                            // wo @ Wv
__device__ float  g_wt [CDIM];                                   // wo @ bv
__device__ float  g_k1 [BATCH * CDIM];                           // rowsum of K
__device__ float  g_wqp[CDIM * CDIM];                            // tf32(wq), A-perm
__device__ float  g_wkp[CDIM * CDIM];                            // tf32(wk), A-perm

// ---------------- helpers --------------------------------------------------
static __device__ __forceinline__ uint32_t to_tf32(float f) {
    uint32_t r;
    asm("cvt.rna.tf32.f32 %0, %1;" : "=r"(r) : "f"(f));
    return r;
}

static __device__ __forceinline__ void mma_tf32(float c[4], const uint4& a, const uint2& b) {
    asm volatile(
        "mma.sync.aligned.m16n8k8.row.col.f32.tf32.tf32.f32 "
        "{%0,%1,%2,%3}, {%4,%5,%6,%7}, {%8,%9}, {%0,%1,%2,%3};"
        : "+f"(c[0]), "+f"(c[1]), "+f"(c[2]), "+f"(c[3])
        : "r"(a.x), "r"(a.y), "r"(a.z), "r"(a.w), "r"(b.x), "r"(b.y));
}

static __device__ __forceinline__ void cp16(uint32_t dst, const void* src) {
    asm volatile("cp.async.cg.shared.global [%0], [%1], 16;" :: "r"(dst), "l"(src));
}
static __device__ __forceinline__ void cp_commit() {
    asm volatile("cp.async.commit_group;" ::: "memory");
}
template <int N> static __device__ __forceinline__ void cp_wait() {
    asm volatile("cp.async.wait_group %0;" :: "n"(N) : "memory");
}

// A-perm word index for (row 0..127, k 0..15) within an 8KB chunk.
// Matches the mainloop frag-load layout (bit-exact with R13/14 staging).
static __device__ __forceinline__ int apw(int row, int k) {
    int w = (((row >> 4) * 2 + (k >> 3)) * 32 + (row & 7) * 4 + (k & 3)) * 4
            + ((row >> 3) & 1) + 2 * ((k >> 2) & 1);
    return w ^ (((row >> 1) & 3) << 2);
}

// C[128,128] += A[128, NC*16] * B(k,n)[NC*16, 128] (tf32-valued fp32).
// A: pre-permuted 8KB chunks in gmem, staged via cp.async (one chunk ahead).
// B: LDG->reg->STS staging (BMODE0: rows=k, ldb/k-row; BMODE1: rows=col,
// k contiguous). 2 stages; 2 CTAs/SM via __launch_bounds__(256,2).
template <int NC, int BMODE>
static __device__ __forceinline__ void mma_block(
    const float* __restrict__ Aperm,
    const float* __restrict__ B, int ldb,
    uint32_t* __restrict__ As, uint32_t* __restrict__ Bs,
    float C[2][8][4])
{
    const int tid = threadIdx.x, lane = tid & 31, wid = tid >> 5;
    const int wm = wid & 3, wn = wid >> 2;
    const uint32_t asb = (uint32_t)__cvta_generic_to_shared(As);

    // ---- B staging mapping + loop-invariant store indices ----
    int bidx[4];
    int b0r0 = 0, b0r1 = 0;
    const int b0n = lane << 2;
    const float* pBbase = B;
    if (BMODE == 0) {
        const int ks = wid >> 2, t = wid & 3;
        b0r0 = ks * 8 + t; b0r1 = b0r0 + 4;
        #pragma unroll
        for (int m = 0; m < 4; m++) {
            const int n = b0n + m;
            const int gg = n & 7, ntl = (n >> 3) & 1, nt2 = n >> 4;
            const int w = ((nt2 * 2 + ks) * 32 + gg * 4 + t) * 4 + ntl * 2;
            bidx[m] = w ^ (((nt2 ^ (gg >> 1)) & 7) << 2);
        }
    } else {
        const int b1col = tid >> 1;
        const int ks = tid & 1;
        const int gg = b1col & 7, ntl = (b1col >> 3) & 1, nt2 = b1col >> 4;
        #pragma unroll
        for (int t = 0; t < 4; t++) {
            const int w = ((nt2 * 2 + ks) * 32 + gg * 4 + t) * 4 + ntl * 2;
            bidx[t] = w ^ (((nt2 ^ (gg >> 1)) & 7) << 2);
        }
        pBbase = B + (size_t)b1col * ldb + ks * 8;
    }

    // ---- precomputed frag word-indices ----
    int afi[2][2], bfi[2][4];
    {
        const int axorf = ((lane >> 3) & 3) << 2;
        #pragma unroll
        for (int mt = 0; mt < 2; mt++)
            #pragma unroll
            for (int ks = 0; ks < 2; ks++)
                afi[mt][ks] = ((((wm * 2 + mt) * 2 + ks) * 32 + lane) * 4) ^ axorf;
        #pragma unroll
        for (int ks = 0; ks < 2; ks++)
            #pragma unroll
            for (int q = 0; q < 4; q++) {
                const int NT2 = wn * 4 + q;
                bfi[ks][q] = (((NT2 * 2 + ks) * 32 + lane) * 4)
                             ^ (((NT2 ^ (lane >> 3)) & 7) << 2);
            }
    }

    float4 rb0, rb1;
    auto prefetchB = [&](int ic) {
        if (BMODE == 0) {
            const int c0 = ic * 16 + b0r0, c1 = c0 + 4;
            rb0 = *(const float4*)(pBbase + (size_t)c0 * ldb + b0n);
            rb1 = *(const float4*)(pBbase + (size_t)c1 * ldb + b0n);
        } else {
            const float* pb = pBbase + ic * 16;
            rb0 = *(const float4*)pb;
            rb1 = *(const float4*)(pb + 4);
        }
    };
    auto issueA = [&](int ic) {
        const float* src = Aperm + (size_t)ic * CHUNK_WORDS + tid * 8;
        const uint32_t dst = asb + (((ic & 1) * CHUNK_WORDS + tid * 8) << 2);
        cp16(dst, src);
        cp16(dst + 16, src + 4);
    };

    issueA(0); cp_commit();
    prefetchB(0);
    #pragma unroll 1
    for (int i = 0; i < NC; i++) {
        uint32_t* Asb = As + (i & 1) * 2048;
        uint32_t* Bsb = Bs + (i & 1) * 2048;
        {   // STS B(i)
            const float v0[4] = {rb0.x, rb0.y, rb0.z, rb0.w};
            const float v1[4] = {rb1.x, rb1.y, rb1.z, rb1.w};
            #pragma unroll
            for (int m = 0; m < 4; m++) {
                uint2 st;
                st.x = __float_as_uint(v0[m]); st.y = __float_as_uint(v1[m]);
                *(uint2*)&Bsb[bidx[m]] = st;
            }
        }
        cp_wait<0>();        // A(i) complete (only group in flight)
        __syncthreads();     // A(i), B(i) visible to all
        if (i + 1 < NC) {    // post-barrier: safe to overwrite other stage
            issueA(i + 1); cp_commit();
            prefetchB(i + 1);
        }
        #pragma unroll
        for (int ks = 0; ks < 2; ks++) {
            uint4 af0 = *(const uint4*)&Asb[afi[0][ks]];
            uint4 af1 = *(const uint4*)&Asb[afi[1][ks]];
            #pragma unroll
            for (int q = 0; q < 4; q++) {
                uint4 bf = *(const uint4*)&Bsb[bfi[ks][q]];
                const uint2 blo = make_uint2(bf.x, bf.y);
                const uint2 bhi = make_uint2(bf.z, bf.w);
                mma_tf32(C[0][2 * q + 0], af0, blo);
                mma_tf32(C[0][2 * q + 1], af0, bhi);
                mma_tf32(C[1][2 * q + 0], af1, blo);
                mma_tf32(C[1][2 * q + 1], af1, bhi);
            }
        }
    }
    __syncthreads();
}

// ---------------------------------------------------------------------------
// K1: GroupNorm stats + h = tf32(GN(x)) fused (group is block-contiguous,
// second loop re-reads from L2). Also zeros g_k1.
// ---------------------------------------------------------------------------
__global__ __launch_bounds__(256) void k_stats(const float* __restrict__ x,
                                               const float* __restrict__ gamma,
                                               const float* __restrict__ beta) {
    const int bg = blockIdx.x;
    if (threadIdx.x < 8) g_k1[bg * 8 + threadIdx.x] = 0.f;
    const float4* p = reinterpret_cast<const float4*>(x + (size_t)bg * 8 * NDIM);
    float s = 0.f, s2 = 0.f;
    for (int i = threadIdx.x; i < 8 * NDIM / 4; i += 256) {
        float4 v = p[i];
        s  += v.x + v.y + v.z + v.w;
        s2 += v.x * v.x + v.y * v.y + v.z * v.z + v.w * v.w;
    }
    __shared__ float sh0[8], sh1[8];
    __shared__ float2 bcast;
    #pragma unroll
    for (int o = 16; o > 0; o >>= 1) {
        s  += __shfl_down_sync(0xffffffffu, s,  o);
        s2 += __shfl_down_sync(0xffffffffu, s2, o);
    }
    const int lane = threadIdx.x & 31, w = threadIdx.x >> 5;
    if (lane == 0) { sh0[w] = s; sh1[w] = s2; }
    __syncthreads();
    if (w == 0) {
        s  = (lane < 8) ? sh0[lane] : 0.f;
        s2 = (lane < 8) ? sh1[lane] : 0.f;
        #pragma unroll
        for (int o = 4; o > 0; o >>= 1) {
            s  += __shfl_down_sync(0xffffffffu, s,  o);
            s2 += __shfl_down_sync(0xffffffffu, s2, o);
        }
        if (lane == 0) {
            const float inv = 1.f / (8.f * NDIM);
            float mean = s * inv;
            float var  = s2 * inv - mean * mean;
            bcast = make_float2(mean, rsqrtf(var + 1e-6f));
        }
    }
    __syncthreads();
    const float mean = bcast.x, rstd = bcast.y;
    const int cbase = (bg & (GRP - 1)) * 8;
    uint4* dst = (uint4*)(g_h + (size_t)bg * 8 * NDIM);
    for (int i = threadIdx.x; i < 8 * NDIM / 4; i += 256) {
        const int ch = cbase + (i >> 10);             // NDIM/4 = 1024
        const float sc = rstd * gamma[ch];
        const float sh = fmaf(-mean, sc, beta[ch]);
        float4 v = p[i];
        uint4 o;
        o.x = to_tf32(fmaf(v.x, sc, sh));
        o.y = to_tf32(fmaf(v.y, sc, sh));
        o.z = to_tf32(fmaf(v.z, sc, sh));
        o.w = to_tf32(fmaf(v.w, sc, sh));
        dst[i] = o;
    }
}

// ---------------------------------------------------------------------------
// K2: U = wo @ Wv, wt = wo @ bv, and A-perm tf32 copies of wq, wk.
// ---------------------------------------------------------------------------
__global__ __launch_bounds__(256) void k_prep(const float* __restrict__ wo,
                                              const float* __restrict__ wv,
                                              const float* __restrict__ bv,
                                              const float* __restrict__ wq,
                                              const float* __restrict__ wk) {
    const int o0 = blockIdx.y * 64, e0 = blockIdx.x * 64;
    const int tid = threadIdx.x;
    const int blk = blockIdx.y * 4 + blockIdx.x;
    // A-perm weight chunks: 32 chunks per matrix; this block does 2.
    #pragma unroll
    for (int c2 = 0; c2 < 2; c2++) {
        const int ch = blk * 2 + c2;
        const int mtile = ch >> 4, kc = ch & 15;
        for (int e = tid; e < 2048; e += 256) {
            const int row = e >> 4, kk = e & 15;
            const int gsrc = (mtile * 128 + row) * CDIM + kc * 16 + kk;
            const int w = ch * CHUNK_WORDS + apw(row, kk);
            g_wqp[w] = __uint_as_float(to_tf32(wq[gsrc]));
            g_wkp[w] = __uint_as_float(to_tf32(wk[gsrc]));
        }
    }
    if (blockIdx.x == 0 && tid < 64) {
        const float* wr = wo + (size_t)(o0 + tid) * CDIM;
        float s = 0.f;
        for (int d = 0; d < CDIM; d += 4) {
            float4 w4 = *(const float4*)(wr + d);
            float4 b4 = *(const float4*)(bv + d);
            s += w4.x * b4.x + w4.y * b4.y + w4.z * b4.z + w4.w * b4.w;
        }
        g_wt[o0 + tid] = s;
    }

    __shared__ float As[16][64];
    __shared__ float Bs[16][64];
    const int arow = tid >> 2, acol = (tid & 3) << 2;
    const int brow = tid >> 4, bcol = (tid & 15) << 2;
    const int tx = (tid & 15) << 2, ty = (tid >> 4) << 2;

    float acc[4][4];
    #pragma unroll
    for (int i = 0; i < 4; i++)
        #pragma unroll
        for (int j = 0; j < 4; j++) acc[i][j] = 0.f;

    for (int k0 = 0; k0 < CDIM; k0 += 16) {
        float4 av = *(const float4*)(wo + (size_t)(o0 + arow) * CDIM + k0 + acol);
        As[acol + 0][arow] = av.x; As[acol + 1][arow] = av.y;
        As[acol + 2][arow] = av.z; As[acol + 3][arow] = av.w;
        *(float4*)&Bs[brow][bcol] =
            *(const float4*)(wv + (size_t)(k0 + brow) * CDIM + e0 + bcol);
        __syncthreads();
        #pragma unroll
        for (int k = 0; k < 16; k++) {
            float4 a4 = *(const float4*)&As[k][ty];
            float4 b4 = *(const float4*)&Bs[k][tx];
            float a[4] = {a4.x, a4.y, a4.z, a4.w};
            float bb[4] = {b4.x, b4.y, b4.z, b4.w};
            #pragma unroll
            for (int i = 0; i < 4; i++)
                #pragma unroll
                for (int j = 0; j < 4; j++)
                    acc[i][j] = fmaf(a[i], bb[j], acc[i][j]);
        }
        __syncthreads();
    }
    #pragma unroll
    for (int i = 0; i < 4; i++)
        *(float4*)(g_U + (size_t)(o0 + ty + i) * CDIM + e0 + tx) =
            make_float4(acc[i][0], acc[i][1], acc[i][2], acc[i][3]);
}

// ---------------------------------------------------------------------------
// K3: Q,K = W_{q,k} @ h (A via cp.async perm chunks, B = h linear).
// Epilogue: bias + elu+1 + tf32 round; Q -> linear g_q; K -> A-perm g_kp
// via SMEM perm staging + coalesced copy-out; K also accumulates k1.
// ---------------------------------------------------------------------------
__global__ __launch_bounds__(256, 2) void k_qkv_t(
    const float* __restrict__ bq, const float* __restrict__ bk) {
    extern __shared__ uint32_t smp[];
    uint32_t* As = smp;            // 2 x 2048
    uint32_t* Bs = smp + 4096;     // 2 x 2048
    const int b  = blockIdx.z;
    const int by = blockIdx.y;            // 0..3
    const int which = by >> 1;            // 0=q 1=k
    const int m0 = (by & 1) * 128;
    const int n0 = blockIdx.x * 128;
    const float* Ap   = (which == 0 ? g_wqp : g_wkp) + (size_t)(m0 >> 7) * 16 * CHUNK_WORDS;
    const float* bias = which == 0 ? bq : bk;

    float C[2][8][4];
    #pragma unroll
    for (int mt = 0; mt < 2; mt++)
        #pragma unroll
        for (int nt = 0; nt < 8; nt++)
            #pragma unroll
            for (int r = 0; r < 4; r++) C[mt][nt][r] = 0.f;

    mma_block<16, 0>(Ap, g_h + (size_t)b * CDIM * NDIM + n0, NDIM, As, Bs, C);

    const int tid = threadIdx.x;
    const int lane = tid & 31, wid = tid >> 5;
    const int g = lane >> 2, t = lane & 3, wm = wid & 3, wn = wid >> 2;
    float rs0[2] = {0.f, 0.f}, rs1[2] = {0.f, 0.f};
    // activation + round (in place), accumulate rowsums
    #pragma unroll
    for (int mt = 0; mt < 2; mt++) {
        const int r0 = wm * 32 + mt * 16 + g;
        const float b0v = bias[m0 + r0], b1v = bias[m0 + r0 + 8];
        #pragma unroll
        for (int nt = 0; nt < 8; nt++) {
            float v0 = C[mt][nt][0] + b0v, v1 = C[mt][nt][1] + b0v;
            float v2 = C[mt][nt][2] + b1v, v3 = C[mt][nt][3] + b1v;
            v0 = (v0 > 0.f) ? (v0 + 1.f) : __expf(v0);
            v1 = (v1 > 0.f) ? (v1 + 1.f) : __expf(v1);
            v2 = (v2 > 0.f) ? (v2 + 1.f) : __expf(v2);
            v3 = (v3 > 0.f) ? (v3 + 1.f) : __expf(v3);
            v0 = __uint_as_float(to_tf32(v0));
            v1 = __uint_as_float(to_tf32(v1));
            v2 = __uint_as_float(to_tf32(v2));
            v3 = __uint_as_float(to_tf32(v3));
            rs0[mt] += v0 + v1; rs1[mt] += v2 + v3;
            C[mt][nt][0] = v0; C[mt][nt][1] = v1;
            C[mt][nt][2] = v2; C[mt][nt][3] = v3;
        }
    }
    if (which == 0) {
        float* outp = g_q + ((size_t)b * CDIM + m0) * NDIM + n0;
        #pragma unroll
        for (int mt = 0; mt < 2; mt++) {
            const int r0 = wm * 32 + mt * 16 + g;
            #pragma unroll
            for (int nt = 0; nt < 8; nt++) {
                const int col = wn * 64 + nt * 8 + 2 * t;
                *(float2*)(outp + (size_t)r0 * NDIM + col)       = make_float2(C[mt][nt][0], C[mt][nt][1]);
                *(float2*)(outp + (size_t)(r0 + 8) * NDIM + col) = make_float2(C[mt][nt][2], C[mt][nt][3]);
            }
        }
    } else {
        // k1 rowsums
        #pragma unroll
        for (int mt = 0; mt < 2; mt++) {
            float a = rs0[mt], c2 = rs1[mt];
            a  += __shfl_xor_sync(0xffffffffu, a,  1);
            a  += __shfl_xor_sync(0xffffffffu, a,  2);
            c2 += __shfl_xor_sync(0xffffffffu, c2, 1);
            c2 += __shfl_xor_sync(0xffffffffu, c2, 2);
            if (t == 0) {
                const int r0 = wm * 32 + mt * 16 + g;
                atomicAdd(&g_k1[b * CDIM + m0 + r0], a);
                atomicAdd(&g_k1[b * CDIM + m0 + r0 + 8], c2);
            }
        }
        // K -> A-perm (rows = c within ctile, k = n): 8 chunks; 2 halves of 4.
        const int ctile = m0 >> 7;
        #pragma unroll 1
        for (int hh = 0; hh < 2; hh++) {
            if (wn == hh) {
                #pragma unroll
                for (int mt = 0; mt < 2; mt++) {
                    const int r0 = wm * 32 + mt * 16 + g;   // ahi(r0)=0
                    #pragma unroll
                    for (int nt = 0; nt < 8; nt++) {
                        const int colb = nt * 8 + 2 * t;    // 0..63 in half
                        uint32_t* cw = smp + (colb >> 4) * 2048;
                        const int kk0 = colb & 15;
                        *(uint2*)&cw[apw(r0, kk0)] =
                            make_uint2(__float_as_uint(C[mt][nt][0]), __float_as_uint(C[mt][nt][2]));
                        *(uint2*)&cw[apw(r0, kk0 + 1)] =
                            make_uint2(__float_as_uint(C[mt][nt][1]), __float_as_uint(C[mt][nt][3]));
                    }
                }
            }
            __syncthreads();
            float* dst = g_kp + ((size_t)((b * 2 + ctile) * 256 + (n0 >> 4) + hh * 4)) * CHUNK_WORDS;
            const uint4* s4 = (const uint4*)smp;
            uint4* d4 = (uint4*)dst;
            #pragma unroll
            for (int j = 0; j < 8; j++) d4[j * 256 + tid] = s4[j * 256 + tid];
            __syncthreads();
        }
    }
}

// ---------------------------------------------------------------------------
// K4: S partials. Sp[sp][b][c][e] = sum_{n in split} K[c,n] * h[e,n].
// A = K perm chunks (cp.async), B = h linear (BMODE1).
// ---------------------------------------------------------------------------
__global__ __launch_bounds__(256, 2) void k_S() {
    extern __shared__ uint32_t smp[];
    uint32_t* As = smp;
    uint32_t* Bs = smp + 4096;
    const int z = blockIdx.z;
    const int b = z / KVSPLIT, sp = z % KVSPLIT;
    const int c0 = blockIdx.y * 128, e0 = blockIdx.x * 128;
    const int nb = sp * (NDIM / KVSPLIT);
    const float* Ap = g_kp + ((size_t)((b * 2 + (c0 >> 7)) * 256 + (nb >> 4))) * CHUNK_WORDS;

    float C[2][8][4];
    #pragma unroll
    for (int mt = 0; mt < 2; mt++)
        #pragma unroll
        for (int nt = 0; nt < 8; nt++)
            #pragma unroll
            for (int r = 0; r < 4; r++) C[mt][nt][r] = 0.f;

    mma_block<(NDIM / KVSPLIT) / 16, 1>(
        Ap, g_h + ((size_t)b * CDIM + e0) * NDIM + nb, NDIM, As, Bs, C);

    const int lane = threadIdx.x & 31, wid = threadIdx.x >> 5;
    const int g = lane >> 2, t = lane & 3, wm = wid & 3, wn = wid >> 2;
    float* dst = g_Sp + ((size_t)sp * BATCH + b) * CDIM * CDIM;
    #pragma unroll
    for (int mt = 0; mt < 2; mt++) {
        const int r0 = c0 + wm * 32 + mt * 16 + g;
        #pragma unroll
        for (int nt = 0; nt < 8; nt++) {
            const int col = e0 + wn * 64 + nt * 8 + 2 * t;
            *(float2*)(dst + (size_t)r0 * CDIM + col)       = make_float2(C[mt][nt][0], C[mt][nt][1]);
            *(float2*)(dst + (size_t)(r0 + 8) * CDIM + col) = make_float2(C[mt][nt][2], C[mt][nt][3]);
        }
    }
}

// ---------------------------------------------------------------------------
// K5: streaming reduction of the 8 S partials.
// ---------------------------------------------------------------------------
__global__ __launch_bounds__(256) void k_red() {
    const size_t i = (size_t)blockIdx.x * 256 + threadIdx.x;
    const size_t SS = (size_t)BATCH * CDIM * CDIM / 4;
    const float4* p = reinterpret_cast<const float4*>(g_Sp);
    float4 a = p[i];
    #pragma unroll
    for (int s = 1; s < KVSPLIT; s++) {
        float4 v = p[i + (size_t)s * SS];
        a.x += v.x; a.y += v.y; a.z += v.z; a.w += v.w;
    }
    reinterpret_cast<float4*>(g_S)[i] = a;
}

// ---------------------------------------------------------------------------
// K6: M[b][o][c] = sum_e U[o,e] S[b][c,e] + wt[o]*k1[b][c], tf32-rounded,
// written directly in A-perm chunk format (rows = o within otile, k = c).
// ---------------------------------------------------------------------------
__global__ __launch_bounds__(256) void k_M() {
    const int b  = blockIdx.z;
    const int o0 = blockIdx.y * 64, c0 = blockIdx.x * 64;
    const float* Sb = g_S + (size_t)b * CDIM * CDIM;

    __shared__ float As[16][64];
    __shared__ float Bs[16][64];
    const int tid  = threadIdx.x;
    const int arow = tid >> 2, acol = (tid & 3) << 2;
    const int tx = (tid & 15) << 2, ty = (tid >> 4) << 2;

    float acc[4][4];
    #pragma unroll
    for (int i = 0; i < 4; i++)
        #pragma unroll
        for (int j = 0; j < 4; j++) acc[i][j] = 0.f;

    for (int k0 = 0; k0 < CDIM; k0 += 16) {
        float4 av = *(const float4*)(g_U + (size_t)(o0 + arow) * CDIM + k0 + acol);
        As[acol + 0][arow] = av.x; As[acol + 1][arow] = av.y;
        As[acol + 2][arow] = av.z; As[acol + 3][arow] = av.w;
        float4 bv = *(const float4*)(Sb + (size_t)(c0 + arow) * CDIM + k0 + acol);
        Bs[acol + 0][arow] = bv.x; Bs[acol + 1][arow] = bv.y;
        Bs[acol + 2][arow] = bv.z; Bs[acol + 3][arow] = bv.w;
        __syncthreads();
        #pragma unroll
        for (int k = 0; k < 16; k++) {
            float4 a4 = *(const float4*)&As[k][ty];
            float4 b4 = *(const float4*)&Bs[k][tx];
            float a[4] = {a4.x, a4.y, a4.z, a4.w};
            float bb[4] = {b4.x, b4.y, b4.z, b4.w};
            #pragma unroll
            for (int i = 0; i < 4; i++)
                #pragma unroll
                for (int j = 0; j < 4; j++)
                    acc[i][j] = fmaf(a[i], bb[j], acc[i][j]);
        }
        __syncthreads();
    }
    const float* k1b = g_k1 + b * CDIM;
    const int otile = o0 >> 7;
    const int kc = (c0 + tx) >> 4;          // tx..tx+3 within one 16-block
    float* chunk = g_Mp + ((size_t)((b * 2 + otile) * 16 + kc)) * CHUNK_WORDS;
    #pragma unroll
    for (int i = 0; i < 4; i++) {
        const int row = (o0 & 127) + ty + i;
        const float w = g_wt[o0 + ty + i];
        #pragma unroll
        for (int j = 0; j < 4; j++) {
            const float val = acc[i][j] + w * k1b[c0 + tx + j];
            chunk[apw(row, (c0 + tx + j) & 15)] = __uint_as_float(to_tf32(val));
        }
    }
}

// ---------------------------------------------------------------------------
// K7: out = x + M @ Q + bo.  A = M perm chunks (cp.async), B = Q linear.
// ---------------------------------------------------------------------------
__global__ __launch_bounds__(256, 2) void k_out_t(const float* __restrict__ x,
                                                  const float* __restrict__ bo,
                                                  float* __restrict__ out) {
    extern __shared__ uint32_t smp[];
    uint32_t* As = smp;
    uint32_t* Bs = smp + 4096;
    const int b  = blockIdx.z;
    const int o0 = blockIdx.y * 128, n0 = blockIdx.x * 128;
    const float* Ap = g_Mp + ((size_t)((b * 2 + (o0 >> 7)) * 16)) * CHUNK_WORDS;
    const float* Qf = g_q + (size_t)b * CDIM * NDIM;

    float C[2][8][4];
    #pragma unroll
    for (int mt = 0; mt < 2; mt++)
        #pragma unroll
        for (int nt = 0; nt < 8; nt++)
            #pragma unroll
            for (int r = 0; r < 4; r++) C[mt][nt][r] = 0.f;

    mma_block<16, 0>(Ap, Qf + n0, NDIM, As, Bs, C);

    const int lane = threadIdx.x & 31, wid = threadIdx.x >> 5;
    const int g = lane >> 2, t = lane & 3, wm = wid & 3, wn = wid >> 2;
    const float* xb = x   + ((size_t)b * CDIM + o0) * NDIM + n0;
    float*       ob = out + ((size_t)b * CDIM + o0) * NDIM + n0;
    #pragma unroll
    for (int mt = 0; mt < 2; mt++) {
        const int r0 = wm * 32 + mt * 16 + g;
        const float b0v = bo[o0 + r0], b1v = bo[o0 + r0 + 8];
        #pragma unroll
        for (int nt = 0; nt < 8; nt++) {
            const int col = wn * 64 + nt * 8 + 2 * t;
            float2 x0 = *(const float2*)(xb + (size_t)r0 * NDIM + col);
            float2 x1 = *(const float2*)(xb + (size_t)(r0 + 8) * NDIM + col);
            *(float2*)(ob + (size_t)r0 * NDIM + col) =
                make_float2(C[mt][nt][0] + b0v + x0.x, C[mt][nt][1] + b0v + x0.y);
            *(float2*)(ob + (size_t)(r0 + 8) * NDIM + col) =
                make_float2(C[mt][nt][2] + b1v + x1.x, C[mt][nt][3] + b1v + x1.y);
        }
    }
}

// ---------------------------------------------------------------------------
#define MMA_SMEM 32768
extern "C" void kernel_launch(void* const* d_in, const int* in_sizes, int n_in,
                              void* d_out, int out_size) {
    const float* x     = (const float*)d_in[0];
    const float* gamma = (const float*)d_in[1];
    const float* beta  = (const float*)d_in[2];
    const float* wq    = (const float*)d_in[3];
    const float* bq    = (const float*)d_in[4];
    const float* wk    = (const float*)d_in[5];
    const float* bk    = (const float*)d_in[6];
    const float* wv    = (const float*)d_in[7];
    const float* bv    = (const float*)d_in[8];
    const float* wo    = (const float*)d_in[9];
    const float* bo    = (const float*)d_in[10];
    float* out = (float*)d_out;

    cudaFuncSetAttribute(k_qkv_t, cudaFuncAttributeMaxDynamicSharedMemorySize, MMA_SMEM);
    cudaFuncSetAttribute(k_S,     cudaFuncAttributeMaxDynamicSharedMemorySize, MMA_SMEM);
    cudaFuncSetAttribute(k_out_t, cudaFuncAttributeMaxDynamicSharedMemorySize, MMA_SMEM);

    k_stats<<<BATCH * GRP, 256>>>(x, gamma, beta);
    k_prep<<<dim3(4, 4), 256>>>(wo, wv, bv, wq, wk);
    k_qkv_t<<<dim3(NDIM / 128, 4, BATCH), 256, MMA_SMEM>>>(bq, bk);
    k_S<<<dim3(2, 2, BATCH * KVSPLIT), 256, MMA_SMEM>>>();
    k_red<<<(BATCH * CDIM * CDIM) / (256 * 4), 256>>>();
    k_M<<<dim3(4, 4, BATCH), 256>>>();
    k_out_t<<<dim3(NDIM / 128, 2, BATCH), 256, MMA_SMEM>>>(x, bo, out);
}